// round 9
// baseline (speedup 1.0000x reference)
#include <cuda_runtime.h>
#include <math.h>

// Problem constants
#define B_TOT 256
#define NBLK  128           // persistent blocks, 1/SM (<=148 co-resident)
#define NTHR  640
#define AIN   8
#define MUL   1024
#define NK    20
#define NO    16
#define PLP   1032          // plane stride (floats)

// Persistent scratch (device globals; allocation-free)
__device__ __align__(16) float g_c[NK * MUL];           // routing coefficients
__device__ __align__(16) float g_bE[NK * MUL];          // accumulated logits b
__device__ __align__(16) float g_part[NBLK * NK * MUL]; // per-block agree partials [blk][k][m]
__device__ unsigned g_cnt = 0;
__device__ unsigned g_rel = 0;

// Packed f32x2 FMA
#define FMA2(acc, a, b) \
    asm("fma.rn.f32x2 %0, %1, %2, %0;" : "+l"(acc) : "l"(a), "l"(b))

__device__ __forceinline__ float pair_sum(unsigned long long u) {
    float lo = __uint_as_float((unsigned)(u & 0xffffffffu));
    float hi = __uint_as_float((unsigned)(u >> 32));
    return lo + hi;
}

#define WARP_RED_SUM(v)                                   \
  do {                                                    \
    v += __shfl_xor_sync(0xffffffffu, v, 16);             \
    v += __shfl_xor_sync(0xffffffffu, v, 8);              \
    v += __shfl_xor_sync(0xffffffffu, v, 4);              \
    v += __shfl_xor_sync(0xffffffffu, v, 2);              \
    v += __shfl_xor_sync(0xffffffffu, v, 1);              \
  } while (0)

// Replay-safe grid barrier (all NBLK blocks co-resident).
// Counter reset by last arriver BEFORE release bump -> g_cnt==0 at exit.
__device__ __forceinline__ void grid_barrier() {
    __threadfence();
    __syncthreads();
    if (threadIdx.x == 0) {
        unsigned r0;
        asm volatile("ld.acquire.gpu.u32 %0, [%1];" : "=r"(r0) : "l"(&g_rel));
        unsigned old = atomicAdd(&g_cnt, 1);
        if (old == NBLK - 1) {
            atomicExch(&g_cnt, 0);
            __threadfence();
            atomicAdd(&g_rel, 1);
        } else {
            unsigned r;
            do {
                __nanosleep(64);
                asm volatile("ld.acquire.gpu.u32 %0, [%1];" : "=r"(r) : "l"(&g_rel));
            } while (r == r0);
        }
        __threadfence();
    }
    __syncthreads();
}

// Shared memory layout (floats):
#define OFF_AGR  16512      // agr [1024][20]           20480
#define OFF_Y    36992      // ysm [2][20][8]             320
#define OFF_SV   37312      // svm [2][320]               640
#define OFF_CQ   37952      // cqm [2][16]                 32
#define OFF_WV   37984      // wvm [2][160]               320
#define OFF_RED  38304      // red scratch                 24
#define SMEM_FLOATS 38336

// ---------------------------------------------------------------------------
// Tail: s = W y, squash coeff (sum over classes per reference), v,
// then wv = W^T v (non-final) or write output (final). Block-local.
// ---------------------------------------------------------------------------
__device__ __forceinline__ void tail_phase(float* sm, const float* __restrict__ W,
                                           float* __restrict__ out, int b0, int final_it)
{
    float* ysm = sm + OFF_Y;
    float* svm = sm + OFF_SV;
    float* cqm = sm + OFF_CQ;
    float* wvm = sm + OFF_WV;
    const int tid = threadIdx.x;
    const int bl = tid / 320, r = tid % 320;
    const int k = r >> 4, o = r & 15;

    const float* wk = W + r * 8;
    const float* yk = ysm + bl * 160 + k * 8;
    float s = 0.f;
    #pragma unroll
    for (int a = 0; a < 8; a++) s += wk[a] * yk[a];
    svm[bl * 320 + r] = s;
    __syncthreads();

    if (tid < 32) {
        int bb = tid >> 4, oo = tid & 15;
        float msq = 0.f;
        #pragma unroll
        for (int kk = 0; kk < NK; kk++) {
            float t = svm[bb * 320 + kk * 16 + oo];
            msq += t * t;
        }
        cqm[bb * 16 + oo] = msq / ((1.f + msq) * sqrtf(msq));
    }
    __syncthreads();

    float v = cqm[bl * 16 + o] * s;
    if (final_it) {
        out[(size_t)(b0 + bl) * 320 + r] = v;
    } else {
        svm[bl * 320 + r] = v;
        __syncthreads();
        if (tid < 320) {
            int bb = tid / 160, rr = tid % 160;
            int kk = rr >> 3, aa = rr & 7;
            float acc = 0.f;
            #pragma unroll
            for (int oo = 0; oo < 16; oo++)
                acc += W[(kk * 16 + oo) * 8 + aa] * svm[bb * 320 + kk * 16 + oo];
            wvm[bb * 160 + rr] = acc;
        }
    }
    __syncthreads();
}

// ---------------------------------------------------------------------------
// Agree phase: agr[m][k] = sum_{bl,a} x[bl][a][m] * wv[bl][k][a] (from SMEM),
// then flush [k][m] partials (scaled 1/256) to g_part[blk] (coalesced STG.128).
// ---------------------------------------------------------------------------
__device__ __forceinline__ void agree_phase(float* sm, int B)
{
    float* xs  = sm;
    float* agr = sm + OFF_AGR;
    float* wvm = sm + OFF_WV;
    const int tid = threadIdx.x;
    const int mqi = tid / NK;       // 0..31
    const int k   = tid % NK;

    unsigned long long wvd[16];
    #pragma unroll
    for (int i = 0; i < 16; i++) {
        unsigned u = __float_as_uint(wvm[(i >> 3) * 160 + k * 8 + (i & 7)]);
        wvd[i] = (unsigned long long)u | ((unsigned long long)u << 32);
    }

    #pragma unroll 2
    for (int r = 0; r < 8; r++) {
        const int m0 = r * 128 + mqi * 4;
        unsigned long long a01 = 0ull, a23 = 0ull;
        #pragma unroll
        for (int i = 0; i < 16; i++) {
            ulonglong2 xv = *(const ulonglong2*)(xs + i * PLP + m0);
            FMA2(a01, xv.x, wvd[i]);
            FMA2(a23, xv.y, wvd[i]);
        }
        float* d = agr + m0 * NK + k;
        d[0]      = pair_sum(0) + __uint_as_float((unsigned)(a01 & 0xffffffffu)) * 0.f
                  + __uint_as_float((unsigned)(a01 & 0xffffffffu)); // lo(a01)
        // (clearer scalar writes below)
        d[0]          = __uint_as_float((unsigned)(a01 & 0xffffffffu));
        d[NK]         = __uint_as_float((unsigned)(a01 >> 32));
        d[2 * NK]     = __uint_as_float((unsigned)(a23 & 0xffffffffu));
        d[3 * NK]     = __uint_as_float((unsigned)(a23 >> 32));
    }
    __syncthreads();

    // flush: transpose smem [m][k] -> global [k][m] float4, scaled by 1/256
    float* gp = g_part + (size_t)B * (NK * MUL);
    #pragma unroll
    for (int i = 0; i < 8; i++) {
        int q  = tid + i * NTHR;          // 0..5119
        int kk = q >> 8, mq = q & 255;
        float4 v;
        v.x = agr[(mq * 4 + 0) * NK + kk];
        v.y = agr[(mq * 4 + 1) * NK + kk];
        v.z = agr[(mq * 4 + 2) * NK + kk];
        v.w = agr[(mq * 4 + 3) * NK + kk];
        v.x *= (1.0f / 256.0f); v.y *= (1.0f / 256.0f);
        v.z *= (1.0f / 256.0f); v.w *= (1.0f / 256.0f);
        *(float4*)(gp + kk * MUL + mq * 4) = v;
    }
}

// ---------------------------------------------------------------------------
// Sa: combine 128 partials for this block's 160 (k,m) outputs -> g_bE.
// ---------------------------------------------------------------------------
__device__ __forceinline__ void combine_phase(float* sm, int B, int accum)
{
    float* psum = sm + OFF_AGR;     // reuse agr region as [4][160]
    const int tid = threadIdx.x;
    const int idxi = tid % 160;
    const int part = tid / 160;     // 0..3
    const int idx  = B * 160 + idxi;

    float acc = 0.f;
    #pragma unroll 8
    for (int blk = part * 32; blk < part * 32 + 32; blk++)
        acc += g_part[(size_t)blk * (NK * MUL) + idx];
    psum[part * 160 + idxi] = acc;
    __syncthreads();

    if (tid < 160) {
        float b = psum[idxi] + psum[160 + idxi] + psum[320 + idxi] + psum[480 + idxi];
        if (accum) b += g_bE[idx];
        g_bE[idx] = b;
    }
    __syncthreads();
}

// ---------------------------------------------------------------------------
// Sb: softmax over m for row k=B (blocks 0..19 active).
// ---------------------------------------------------------------------------
__device__ __forceinline__ void softmax_phase(float* sm, int B)
{
    if (B >= NK) return;
    float* red = sm + OFF_RED;
    const int tid = threadIdx.x;
    const int lane = tid & 31, wp = tid >> 5;
    const float* brow = g_bE + B * MUL;

    float v1 = brow[tid];
    float v2 = (tid < 384) ? brow[640 + tid] : -3.4e38f;

    float mx = fmaxf(v1, v2);
    #pragma unroll
    for (int off = 16; off; off >>= 1)
        mx = fmaxf(mx, __shfl_xor_sync(0xffffffffu, mx, off));
    if (lane == 0) red[wp] = mx;
    __syncthreads();
    if (tid < 32) {
        float m = (tid < 20) ? red[tid] : -3.4e38f;
        #pragma unroll
        for (int off = 16; off; off >>= 1)
            m = fmaxf(m, __shfl_xor_sync(0xffffffffu, m, off));
        if (tid == 0) red[20] = m;
    }
    __syncthreads();
    mx = red[20];
    __syncthreads();

    float e1 = expf(v1 - mx);
    float e2 = (tid < 384) ? expf(v2 - mx) : 0.f;
    float s = e1 + e2;
    #pragma unroll
    for (int off = 16; off; off >>= 1)
        s += __shfl_xor_sync(0xffffffffu, s, off);
    if (lane == 0) red[wp] = s;
    __syncthreads();
    if (tid < 32) {
        float ss = (tid < 20) ? red[tid] : 0.f;
        #pragma unroll
        for (int off = 16; off; off >>= 1)
            ss += __shfl_xor_sync(0xffffffffu, ss, off);
        if (tid == 0) red[20] = ss;
    }
    __syncthreads();
    float inv = 1.0f / red[20];

    g_c[B * MUL + tid] = e1 * inv;
    if (tid < 384) g_c[B * MUL + 640 + tid] = e2 * inv;
}

// ---------------------------------------------------------------------------
// Y phase: y[bl][k][a] = sum_m c[k][m] * x[bl][a][m]; x from SMEM, c from L2.
// 20 warps = (bl, kquad, ahalf); acc[4][4] u64 = 32 regs.
// ---------------------------------------------------------------------------
__device__ __forceinline__ void y_phase(float* sm)
{
    float* xs  = sm;
    float* ysm = sm + OFF_Y;
    const int tid = threadIdx.x;
    const int w = tid >> 5, lane = tid & 31;
    const int bl = w / 10;
    const int r  = w % 10;
    const int k0 = (r >> 1) * 4;
    const int a0 = (r & 1) * 4;

    unsigned long long acc[4][4];
    #pragma unroll
    for (int kk = 0; kk < 4; kk++)
        #pragma unroll
        for (int aa = 0; aa < 4; aa++) acc[kk][aa] = 0ull;

    #pragma unroll 2
    for (int j = 0; j < 8; j++) {
        const int m = j * 128 + lane * 4;
        ulonglong2 ck0 = *(const ulonglong2*)(g_c + (k0 + 0) * MUL + m);
        ulonglong2 ck1 = *(const ulonglong2*)(g_c + (k0 + 1) * MUL + m);
        ulonglong2 ck2 = *(const ulonglong2*)(g_c + (k0 + 2) * MUL + m);
        ulonglong2 ck3 = *(const ulonglong2*)(g_c + (k0 + 3) * MUL + m);
        #pragma unroll
        for (int aa = 0; aa < 4; aa++) {
            ulonglong2 xv = *(const ulonglong2*)(xs + (bl * 8 + a0 + aa) * PLP + m);
            FMA2(acc[0][aa], ck0.x, xv.x); FMA2(acc[0][aa], ck0.y, xv.y);
            FMA2(acc[1][aa], ck1.x, xv.x); FMA2(acc[1][aa], ck1.y, xv.y);
            FMA2(acc[2][aa], ck2.x, xv.x); FMA2(acc[2][aa], ck2.y, xv.y);
            FMA2(acc[3][aa], ck3.x, xv.x); FMA2(acc[3][aa], ck3.y, xv.y);
        }
    }
    #pragma unroll
    for (int kk = 0; kk < 4; kk++) {
        #pragma unroll
        for (int aa = 0; aa < 4; aa++) {
            float v = pair_sum(acc[kk][aa]);
            WARP_RED_SUM(v);
            if (lane == 0) ysm[bl * 160 + (k0 + kk) * 8 + a0 + aa] = v;
        }
    }
    __syncthreads();
}

// ---------------------------------------------------------------------------
// Persistent kernel: P(+tail0) | A0 | Sa0 | Sb0 | Y1+tail1 | A1 | Sa1 | Sb1 |
// Y2+tail2(out).
// ---------------------------------------------------------------------------
__global__ void __launch_bounds__(NTHR, 1)
capsule_kernel(const float* __restrict__ x, const float* __restrict__ W,
               float* __restrict__ out)
{
    extern __shared__ float sm[];
    float* xs  = sm;
    float* ysm = sm + OFF_Y;
    float* red = sm + OFF_RED;
    const int tid = threadIdx.x;
    const int B   = blockIdx.x;
    const int b0  = B * 2;

    // ===== P: stage + transpose x into SMEM planes; y0 = mean_m x =====
    {
        const float4* xsrc = (const float4*)(x + (size_t)b0 * 8192);
        for (int i = tid; i < 4096; i += NTHR) {
            int bl = i >> 11, f = i & 2047;
            int m = f >> 1, half = f & 1;
            float4 v = xsrc[i];
            float* base = xs + (bl * 8 + half * 4) * PLP + m;
            base[0 * PLP] = v.x; base[1 * PLP] = v.y;
            base[2 * PLP] = v.z; base[3 * PLP] = v.w;
        }
        __syncthreads();

        // plane sums (16 warps = (bl,a))
        const int w = tid >> 5, lane = tid & 31;
        if (w < 16) {
            float s = 0.f;
            #pragma unroll 8
            for (int t = 0; t < 32; t++)
                s += xs[w * PLP + t * 32 + lane];
            WARP_RED_SUM(s);
            if (lane == 0) red[w] = s;
        }
        __syncthreads();
        if (tid < 320) {
            int bl = tid / 160, rr = tid % 160;
            ysm[bl * 160 + rr] = red[bl * 8 + (rr & 7)] * (1.0f / 1024.0f);
        }
        __syncthreads();
        tail_phase(sm, W, out, b0, 0);       // iter-0 tail -> wv0
    }

    grid_barrier();
    agree_phase(sm, B);                      // A0
    grid_barrier();
    combine_phase(sm, B, 0);                 // Sa0
    grid_barrier();
    softmax_phase(sm, B);                    // Sb0 -> c1
    grid_barrier();

    y_phase(sm);                             // Y1
    tail_phase(sm, W, out, b0, 0);           // tail1 -> wv1
    grid_barrier();
    agree_phase(sm, B);                      // A1
    grid_barrier();
    combine_phase(sm, B, 1);                 // Sa1
    grid_barrier();
    softmax_phase(sm, B);                    // Sb1 -> c2
    grid_barrier();

    y_phase(sm);                             // Y2
    tail_phase(sm, W, out, b0, 1);           // final -> out
}

// ---------------------------------------------------------------------------
extern "C" void kernel_launch(void* const* d_in, const int* in_sizes, int n_in,
                              void* d_out, int out_size)
{
    const float* x = (const float*)d_in[0];   // [256][1024][8] flat view
    const float* W = (const float*)d_in[1];   // [20][16][8]
    float* out = (float*)d_out;               // [256][20][16][1]

    const int SMEM = SMEM_FLOATS * (int)sizeof(float);   // ~150 KB
    cudaFuncSetAttribute(capsule_kernel,
                         cudaFuncAttributeMaxDynamicSharedMemorySize, SMEM);

    capsule_kernel<<<NBLK, NTHR, SMEM>>>(x, W, out);
}

// round 10
// speedup vs baseline: 1.2792x; 1.2792x over previous
#include <cuda_runtime.h>
#include <math.h>

// Problem constants
#define B_TOT 256
#define AIN   8
#define MUL   1024
#define NK    20
#define NO    16
#define PLF   1036          // plane stride (floats): 16B-aligned, kills STS h-conflict

// Persistent scratch (device globals; allocation-free)
__device__ __align__(16) float g_c[NK * MUL];
__device__ __align__(16) float g_b[NK * MUL];
__device__ __align__(16) float g_bpart[16 * NK * MUL];
__device__ __align__(16) float g_wv[B_TOT * NK * AIN];

// Packed f32x2 FMA
#define FMA2(acc, a, b) \
    asm("fma.rn.f32x2 %0, %1, %2, %0;" : "+l"(acc) : "l"(a), "l"(b))

__device__ __forceinline__ float pair_sum(unsigned long long u) {
    float lo = __uint_as_float((unsigned)(u & 0xffffffffu));
    float hi = __uint_as_float((unsigned)(u >> 32));
    return lo + hi;
}

#define WARP_RED_SUM(v)                                   \
  do {                                                    \
    v += __shfl_xor_sync(0xffffffffu, v, 16);             \
    v += __shfl_xor_sync(0xffffffffu, v, 8);              \
    v += __shfl_xor_sync(0xffffffffu, v, 4);              \
    v += __shfl_xor_sync(0xffffffffu, v, 2);              \
    v += __shfl_xor_sync(0xffffffffu, v, 1);              \
  } while (0)

// F smem layout (floats)
#define OFF_CS   16576      // cs  [20][1024]   20480
#define OFF_Y    37056      // ysm [2][20][8]     320
#define OFF_SV   37376      // svm [2][320]       640
#define OFF_CQ   38016      // cqm [2][16]         32
#define OFF_RED  38048      // red [16]            16
#define F_FLOATS 38080
#define F_THREADS 640

// ---------------------------------------------------------------------------
// F kernel: block = batch-pair. Stage x (transposed to planes) + c into SMEM,
// y = c^T x entirely from SMEM, then tail: s = W y, squash, v, wv/out.
// ---------------------------------------------------------------------------
__global__ void __launch_bounds__(F_THREADS, 1)
fused_kernel(const float* __restrict__ x, const float* __restrict__ W,
             float* __restrict__ out, int uniform_c, int final_iter)
{
    extern __shared__ float sm[];
    float* xs  = sm;                 // [2][8][PLF]
    float* cs  = sm + OFF_CS;        // [20][1024]
    float* ysm = sm + OFF_Y;
    float* svm = sm + OFF_SV;
    float* cqm = sm + OFF_CQ;
    float* red = sm + OFF_RED;

    const int tid = threadIdx.x;
    const int b0  = blockIdx.x * 2;

    // ---- stage x transposed (f4 load -> 4 scalar STS to planes) ----
    {
        const float4* xsrc = (const float4*)(x + (size_t)b0 * 8192);
        #pragma unroll 2
        for (int i = tid; i < 4096; i += F_THREADS) {
            int bl = i >> 11, f = i & 2047;
            int m = f >> 1, half = f & 1;
            float4 v = xsrc[i];
            float* base = xs + (bl * 8 + half * 4) * PLF + m;
            base[0 * PLF] = v.x; base[1 * PLF] = v.y;
            base[2 * PLF] = v.z; base[3 * PLF] = v.w;
        }
    }
    // ---- stage c (bulk f4 copy; skipped on uniform iteration 0) ----
    if (!uniform_c) {
        const float4* csrc = (const float4*)g_c;
        float4* cdst = (float4*)cs;
        #pragma unroll
        for (int i = 0; i < 8; i++) cdst[tid + i * F_THREADS] = csrc[tid + i * F_THREADS];
    }
    __syncthreads();

    // ---- y phase ----
    if (uniform_c) {
        // y0[a] = mean_m x ; 16 warps = (bl, a)
        const int w = tid >> 5, lane = tid & 31;
        if (w < 16) {
            const float* pl = xs + w * PLF;
            float s = 0.f;
            #pragma unroll 8
            for (int t = 0; t < 32; t++) s += pl[t * 32 + lane];
            WARP_RED_SUM(s);
            if (lane == 0) red[w] = s;
        }
        __syncthreads();
        if (tid < 320) {
            int bl = tid / 160, rr = tid % 160;
            ysm[bl * 160 + rr] = red[bl * 8 + (rr & 7)] * (1.0f / 1024.0f);
        }
        __syncthreads();
    } else {
        // 20 warps = (bl, kq, ah); 4 classes x 4 atoms, f32x2, all SMEM operands
        const int w = tid >> 5, lane = tid & 31;
        const int bl = w / 10;
        const int r  = w % 10;
        const int k0 = (r >> 1) * 4;
        const int a0 = (r & 1) * 4;

        unsigned long long acc[4][4];
        #pragma unroll
        for (int kk = 0; kk < 4; kk++)
            #pragma unroll
            for (int aa = 0; aa < 4; aa++) acc[kk][aa] = 0ull;

        #pragma unroll 2
        for (int j = 0; j < 8; j++) {
            const int m = j * 128 + lane * 4;
            ulonglong2 ck0 = *(const ulonglong2*)(cs + (k0 + 0) * MUL + m);
            ulonglong2 ck1 = *(const ulonglong2*)(cs + (k0 + 1) * MUL + m);
            ulonglong2 ck2 = *(const ulonglong2*)(cs + (k0 + 2) * MUL + m);
            ulonglong2 ck3 = *(const ulonglong2*)(cs + (k0 + 3) * MUL + m);
            #pragma unroll
            for (int aa = 0; aa < 4; aa++) {
                ulonglong2 xv = *(const ulonglong2*)(xs + (bl * 8 + a0 + aa) * PLF + m);
                FMA2(acc[0][aa], ck0.x, xv.x); FMA2(acc[0][aa], ck0.y, xv.y);
                FMA2(acc[1][aa], ck1.x, xv.x); FMA2(acc[1][aa], ck1.y, xv.y);
                FMA2(acc[2][aa], ck2.x, xv.x); FMA2(acc[2][aa], ck2.y, xv.y);
                FMA2(acc[3][aa], ck3.x, xv.x); FMA2(acc[3][aa], ck3.y, xv.y);
            }
        }
        #pragma unroll
        for (int kk = 0; kk < 4; kk++) {
            #pragma unroll
            for (int aa = 0; aa < 4; aa++) {
                float v = pair_sum(acc[kk][aa]);
                WARP_RED_SUM(v);
                if (lane == 0) ysm[bl * 160 + (k0 + kk) * 8 + a0 + aa] = v;
            }
        }
        __syncthreads();
    }

    // ---- tail: s = W y, squash (sum over classes per reference), v, wv/out ----
    const int bl = tid / 320, r = tid % 320;
    const int k = r >> 4, o = r & 15;
    {
        const float* wk = W + r * 8;
        const float* yk = ysm + bl * 160 + k * 8;
        float s = 0.f;
        #pragma unroll
        for (int a = 0; a < 8; a++) s += wk[a] * yk[a];
        svm[bl * 320 + r] = s;
        __syncthreads();

        if (tid < 32) {
            int bb = tid >> 4, oo = tid & 15;
            float msq = 0.f;
            #pragma unroll
            for (int kk = 0; kk < NK; kk++) {
                float t = svm[bb * 320 + kk * 16 + oo];
                msq += t * t;
            }
            cqm[bb * 16 + oo] = msq / ((1.f + msq) * sqrtf(msq));
        }
        __syncthreads();

        float v = cqm[bl * 16 + o] * s;
        if (final_iter) {
            out[(size_t)(b0 + bl) * 320 + r] = v;     // coalesced
        } else {
            svm[bl * 320 + r] = v;
            __syncthreads();
            if (tid < 320) {
                int bb = tid / 160, rr = tid % 160;
                int kk = rr >> 3, aa = rr & 7;
                float acc = 0.f;
                #pragma unroll
                for (int oo = 0; oo < 16; oo++)
                    acc += W[(kk * 16 + oo) * 8 + aa] * svm[bb * 320 + kk * 16 + oo];
                g_wv[(size_t)(b0 + bb) * 160 + rr] = acc;
            }
        }
    }
}

// ---------------------------------------------------------------------------
// Update kernel (R7): 256 blocks = (16 m-tiles x 16 slices of 16 batches).
// partial[m,k] = sum_{b in slice} sum_a x[b,m,a]*wv[b,k,a] / 256
// ---------------------------------------------------------------------------
#define U_THREADS 320

__global__ void __launch_bounds__(U_THREADS)
update_kernel(const float* __restrict__ x)
{
    __shared__ float xsU[8 * 512];
    __shared__ float wvs[8 * 160];

    const int tid   = threadIdx.x;
    const int m0    = blockIdx.x * 64;
    const int bbase = blockIdx.y * 16;
    const int mi4   = tid / NK;
    const int k     = tid % NK;

    unsigned long long acc[4];
    #pragma unroll
    for (int i = 0; i < 4; i++) acc[i] = 0ull;

    for (int c0 = 0; c0 < 16; c0 += 8) {
        __syncthreads();
        for (int i = tid; i < 1024; i += U_THREADS) {
            int bi = i >> 7, rr = i & 127;
            ((float4*)(xsU + bi * 512))[rr] =
                ((const float4*)(x + (size_t)(bbase + c0 + bi) * 8192 + m0 * 8))[rr];
        }
        for (int i = tid; i < 320; i += U_THREADS) {
            int bi = i / 40, rr = i % 40;
            ((float4*)(wvs + bi * 160))[rr] =
                ((const float4*)(g_wv + (size_t)(bbase + c0 + bi) * 160))[rr];
        }
        __syncthreads();

        #pragma unroll
        for (int bi = 0; bi < 8; bi++) {
            const ulonglong2* wp = (const ulonglong2*)(wvs + bi * 160 + k * 8);
            ulonglong2 wA = wp[0], wB = wp[1];
            const ulonglong2* xp = (const ulonglong2*)(xsU + bi * 512 + mi4 * 32);
            #pragma unroll
            for (int mm = 0; mm < 4; mm++) {
                ulonglong2 xA = xp[mm * 2];
                ulonglong2 xB = xp[mm * 2 + 1];
                FMA2(acc[mm], xA.x, wA.x);
                FMA2(acc[mm], xA.y, wA.y);
                FMA2(acc[mm], xB.x, wB.x);
                FMA2(acc[mm], xB.y, wB.y);
            }
        }
    }

    float* dst = g_bpart + (size_t)blockIdx.y * (NK * MUL) + k * MUL + m0 + mi4 * 4;
    #pragma unroll
    for (int mm = 0; mm < 4; mm++) dst[mm] = pair_sum(acc[mm]) * (1.0f / 256.0f);
}

// ---------------------------------------------------------------------------
// Softmax kernel (R7): 20 blocks x 1024 threads (thread per m).
// ---------------------------------------------------------------------------
__global__ void __launch_bounds__(1024)
softmax_kernel(int accum)
{
    const int k = blockIdx.x;
    const int t = threadIdx.x;
    const int lane = t & 31, wp = t >> 5;
    __shared__ float red[32];
    __shared__ float bc;

    float b = accum ? g_b[k * MUL + t] : 0.f;
    #pragma unroll
    for (int p = 0; p < 16; p++) b += g_bpart[p * NK * MUL + k * MUL + t];
    g_b[k * MUL + t] = b;

    float mx = b;
    #pragma unroll
    for (int off = 16; off; off >>= 1)
        mx = fmaxf(mx, __shfl_xor_sync(0xffffffffu, mx, off));
    if (lane == 0) red[wp] = mx;
    __syncthreads();
    if (t < 32) {
        float m = red[t];
        #pragma unroll
        for (int off = 16; off; off >>= 1)
            m = fmaxf(m, __shfl_xor_sync(0xffffffffu, m, off));
        if (t == 0) bc = m;
    }
    __syncthreads();
    mx = bc;

    float e = expf(b - mx);
    float s = e;
    #pragma unroll
    for (int off = 16; off; off >>= 1)
        s += __shfl_xor_sync(0xffffffffu, s, off);
    __syncthreads();
    if (lane == 0) red[wp] = s;
    __syncthreads();
    if (t < 32) {
        float ss = red[t];
        #pragma unroll
        for (int off = 16; off; off >>= 1)
            ss += __shfl_xor_sync(0xffffffffu, ss, off);
        if (t == 0) bc = ss;
    }
    __syncthreads();

    g_c[k * MUL + t] = e * (1.0f / bc);
}

// ---------------------------------------------------------------------------
extern "C" void kernel_launch(void* const* d_in, const int* in_sizes, int n_in,
                              void* d_out, int out_size)
{
    const float* x = (const float*)d_in[0];   // [256][1024][8] flat view
    const float* W = (const float*)d_in[1];   // [20][16][8]
    float* out = (float*)d_out;               // [256][20][16][1]

    const int F_SMEM = F_FLOATS * (int)sizeof(float);   // ~152 KB
    cudaFuncSetAttribute(fused_kernel,
                         cudaFuncAttributeMaxDynamicSharedMemorySize, F_SMEM);

    dim3 ugrid(16, 16);

    // iteration 0 (uniform c, no c staging)
    fused_kernel<<<B_TOT / 2, F_THREADS, F_SMEM>>>(x, W, out, 1, 0);
    update_kernel<<<ugrid, U_THREADS>>>(x);
    softmax_kernel<<<NK, 1024>>>(0);

    // iteration 1
    fused_kernel<<<B_TOT / 2, F_THREADS, F_SMEM>>>(x, W, out, 0, 0);
    update_kernel<<<ugrid, U_THREADS>>>(x);
    softmax_kernel<<<NK, 1024>>>(1);

    // iteration 2 (final -> write v)
    fused_kernel<<<B_TOT / 2, F_THREADS, F_SMEM>>>(x, W, out, 0, 1);
}